// round 14
// baseline (speedup 1.0000x reference)
#include <cuda_runtime.h>
#include <cuda_bf16.h>
#include <cstdint>

// ---------------------------------------------------------------------------
//   y   = W @ x + b   (oc=128, cin=128, vox=186624)
//   out = leaky_0.2( y * (y + att[c,l,pp]/nz[c,l] + 1) )
// GEMM on mma.sync m16n8k16 (bf16) via 3-way split: Wh*xh + Wh*xl + Wl*xh
// R14: prep parallelism doubled (9216 CTAs, one 4-row group per warp,
//      32-row half-slabs); fused = R13 + streaming out stores (__stcs).
// ---------------------------------------------------------------------------

#define CIN    128
#define COUT   128
#define HWDIM  5184
#define NVOX   186624
#define PATCH  9
#define PPSQ   81
#define NW     576
#define LPATCH 2304

#define TILE_V  64
#define NT64    2916          // NVOX / 64
#define GRID    296           // 2 CTAs per SM
#define THREADS 256

// per-CTA dynamic smem (bytes):
//   x stage: xh 16KB @0, xl 16KB @16384 (reused as 32KB fp32 out-stage)
//   W: Wh 32KB @32768, Wl 32KB @65536
#define SM_XH 0
#define SM_XL 16384
#define SM_W  32768
#define SMEM_TOTAL 98304      // 96KB -> 2 CTAs/SM

__device__ __align__(16) unsigned short g_Wsw[32768];        // [Wh][Wl], swizzled
__device__ __align__(16) unsigned short g_atts2[COUT * NVOX]; // bf16 att/nz, voxel-major

// ---------------------------------------------------------------------------
// helpers
// ---------------------------------------------------------------------------
__device__ __forceinline__ uint32_t smem_u32(const void* p) {
    uint32_t a;
    asm("{ .reg .u64 t; cvta.to.shared.u64 t, %1; cvt.u32.u64 %0, t; }"
        : "=r"(a) : "l"(p));
    return a;
}
__device__ __forceinline__ uint32_t pack_bf16x2(float lo, float hi) {
    uint32_t r;
    asm("cvt.rn.bf16x2.f32 %0, %1, %2;" : "=r"(r) : "f"(hi), "f"(lo));
    return r;
}
__device__ __forceinline__ int redux_add(int v) {
    int r;
    asm("redux.sync.add.s32 %0, %1, 0xffffffff;" : "=r"(r) : "r"(v));
    return r;
}
__device__ __forceinline__ void sts128(uint32_t addr, uint32_t a, uint32_t b,
                                       uint32_t c, uint32_t d) {
    asm volatile("st.shared.v4.u32 [%0], {%1, %2, %3, %4};"
                 :: "r"(addr), "r"(a), "r"(b), "r"(c), "r"(d) : "memory");
}
__device__ __forceinline__ void sts64f(uint32_t addr, float a, float b) {
    asm volatile("st.shared.v2.f32 [%0], {%1, %2};"
                 :: "r"(addr), "f"(a), "f"(b) : "memory");
}
__device__ __forceinline__ float4 lds128f(uint32_t addr) {
    float4 v;
    asm volatile("ld.shared.v4.f32 {%0,%1,%2,%3}, [%4];"
                 : "=f"(v.x), "=f"(v.y), "=f"(v.z), "=f"(v.w) : "r"(addr));
    return v;
}
__device__ __forceinline__ void ldsm_x4(uint32_t addr, uint32_t* r) {
    asm volatile("ldmatrix.sync.aligned.m8n8.x4.shared.b16 {%0,%1,%2,%3}, [%4];"
                 : "=r"(r[0]), "=r"(r[1]), "=r"(r[2]), "=r"(r[3]) : "r"(addr));
}
__device__ __forceinline__ void ldsm_x4_t(uint32_t addr, uint32_t* r) {
    asm volatile("ldmatrix.sync.aligned.m8n8.x4.trans.shared.b16 {%0,%1,%2,%3}, [%4];"
                 : "=r"(r[0]), "=r"(r[1]), "=r"(r[2]), "=r"(r[3]) : "r"(addr));
}
__device__ __forceinline__ void mma16816(float* d, const uint32_t* a,
                                         uint32_t b0, uint32_t b1) {
    asm volatile(
        "mma.sync.aligned.m16n8k16.row.col.f32.bf16.bf16.f32 "
        "{%0,%1,%2,%3}, {%4,%5,%6,%7}, {%8,%9}, {%0,%1,%2,%3};"
        : "+f"(d[0]), "+f"(d[1]), "+f"(d[2]), "+f"(d[3])
        : "r"(a[0]), "r"(a[1]), "r"(a[2]), "r"(a[3]), "r"(b0), "r"(b1));
}
__device__ __forceinline__ unsigned long long ldg_u64(const void* p) {
    unsigned long long v;
    asm volatile("ld.global.nc.u64 %0, [%1];" : "=l"(v) : "l"(p));
    return v;
}
__device__ __forceinline__ float bf2f(uint32_t v16) {
    return __uint_as_float(v16 << 16);
}
__device__ __forceinline__ float sel4(int r, float a, float b, float c, float d) {
    float v = a;
    v = (r == 1) ? b : v;
    v = (r == 2) ? c : v;
    v = (r == 3) ? d : v;
    return v;
}
__device__ __forceinline__ float leaky_ep(float y, float a) {
    float o = y * (y + a + 1.0f);
    return (o >= 0.0f) ? o : 0.2f * o;
}
// W-tile swizzle (256B rows, verified)
__device__ __forceinline__ uint32_t swz(int row, uint32_t colbyte) {
    return (uint32_t)row * 256u + (colbyte ^ (uint32_t)((row & 7) << 4));
}

// ---------------------------------------------------------------------------
// Prep v5: W split (verified) + att -> voxel-major bf16(att/nz).
// 9216 CTAs: CTA = (oc, id, iwb, half) -> 32 patch-rows. Warp = one 4-row
// group (register-retained, redux counts), STS.16 scatter into 5KB staging,
// coalesced uint4 copy-out.
// ---------------------------------------------------------------------------
__device__ __forceinline__ void prep_group(const float4* a4, int g, int lane,
                                           unsigned short* obuf)
{
    float4 f[3];
#pragma unroll
    for (int p = 0; p < 3; p++) {
        int idx = p * 32 + lane;
        if (idx < 81) f[p] = __ldg(a4 + idx);
    }

    // counts per row (verified logic)
    int c0 = 0, c1 = 0, c2 = 0, c3 = 0;
#pragma unroll
    for (int p = 0; p < 3; p++) {
        int idx = p * 32 + lane;
        if (idx < 81) {
            float4 q = f[p];
            int e = idx * 4;
            int r0 = (e >= 81) + (e >= 162) + (e >= 243);
            int r3 = (e + 3 >= 81) + (e + 3 >= 162) + (e + 3 >= 243);
            if (r0 == r3) {
                int cnt = (q.x != 0.f) + (q.y != 0.f) + (q.z != 0.f) + (q.w != 0.f);
                c0 += (r0 == 0) ? cnt : 0;
                c1 += (r0 == 1) ? cnt : 0;
                c2 += (r0 == 2) ? cnt : 0;
                c3 += (r0 == 3) ? cnt : 0;
            } else {
                float vv[4] = { q.x, q.y, q.z, q.w };
#pragma unroll
                for (int j = 0; j < 4; j++) {
                    int ej = e + j;
                    int rj = (ej >= 81) + (ej >= 162) + (ej >= 243);
                    int nz = (vv[j] != 0.f);
                    c0 += (rj == 0) ? nz : 0;
                    c1 += (rj == 1) ? nz : 0;
                    c2 += (rj == 2) ? nz : 0;
                    c3 += (rj == 3) ? nz : 0;
                }
            }
        }
    }
    c0 = redux_add(c0); c1 = redux_add(c1);
    c2 = redux_add(c2); c3 = redux_add(c3);
    float i0 = 1.0f / ((float)c0 + 1e-5f);
    float i1 = 1.0f / ((float)c1 + 1e-5f);
    float i2 = 1.0f / ((float)c2 + 1e-5f);
    float i3 = 1.0f / ((float)c3 + 1e-5f);

    // scale + scatter into voxel-major staging: obuf[pd*288 + row*9 + pw]
#pragma unroll
    for (int p = 0; p < 3; p++) {
        int idx = p * 32 + lane;
        if (idx < 81) {
            float4 q = f[p];
            float vv[4] = { q.x, q.y, q.z, q.w };
            int e = idx * 4;
#pragma unroll
            for (int j = 0; j < 4; j++) {
                int ej = e + j;
                int rj = (ej >= 81) + (ej >= 162) + (ej >= 243);
                int ppj = ej - rj * 81;
                int pd = ppj / 9;
                int pw = ppj - pd * 9;
                int row = g * 4 + rj;          // local row 0..31
                float s = sel4(rj, i0, i1, i2, i3);
                __nv_bfloat16 u = __float2bfloat16(vv[j] * s);
                obuf[pd * 288 + row * 9 + pw] = *(unsigned short*)&u;
            }
        }
    }
}

__global__ __launch_bounds__(256) void prep_kernel(const float* __restrict__ att,
                                                   const float* __restrict__ W)
{
    __shared__ unsigned short obuf[9 * 288];   // 5184 B staging

    const int tid = threadIdx.x;
    const int blk = blockIdx.x;

    if (blk < 64) {   // W split (verified)
        int idx = blk * 256 + tid;
        int oc = idx >> 7, k = idx & 127;
        float w = W[idx];
        __nv_bfloat16 h = __float2bfloat16(w);
        float hf = __bfloat162float(h);
        __nv_bfloat16 l = __float2bfloat16(w - hf);
        uint32_t off = swz(oc, (uint32_t)(k * 2)) >> 1;
        g_Wsw[off]         = *(unsigned short*)&h;
        g_Wsw[off + 16384] = *(unsigned short*)&l;
    }

    // blk -> (oc, id, iwb, half): 72 blocks per oc
    const int oc   = blk / 72;
    const int rem  = blk - oc * 72;
    const int id   = rem / 18;
    const int rem2 = rem - id * 18;
    const int iwb  = rem2 >> 1;
    const int half = rem2 & 1;
    const int row0 = iwb * 64 + half * 32;    // starting iw within the 576

    const int wid = tid >> 5;
    const int lane = tid & 31;

    // slab base: 32 rows x 81 floats
    const float4* slab = (const float4*)(att
        + (size_t)(oc * LPATCH + id * 576 + row0) * PPSQ);

    // warp handles group wid (4 rows)
    prep_group(slab + (size_t)wid * 81, wid, lane, obuf);
    __syncthreads();

    // coalesced copy-out (324 uint4): dst offset = pd*HWDIM + row0*9 + w*8
    {
        const uint4* src = (const uint4*)obuf;
        unsigned short* dstbase = g_atts2
            + (size_t)oc * NVOX + (size_t)(id * 9) * HWDIM + row0 * 9;
        for (int q = tid; q < 324; q += 256) {
            int pd = q / 36;
            int w  = q - pd * 36;
            *(uint4*)(dstbase + (size_t)pd * HWDIM + w * 8) = src[q];
        }
    }
}

// ---------------------------------------------------------------------------
// Fused persistent kernel: CTA = 128 oc x 64 vox, 8 warps (4 oc x 2 vox),
// warp tile 32 oc x 32 vox, single-buffered x, 2 CTAs/SM, smem out-restage.
// (R13 verbatim + __stcs on output)
// ---------------------------------------------------------------------------
struct XFrag { float4 f[8]; };

// thread = 4 k-rows x 8 consecutive vox (verified)
__device__ __forceinline__ void ldg_tile(const float* __restrict__ x,
                                         int v0, int wid, int lane, XFrag& r)
{
    const int k0 = wid * 16 + (lane >> 3) * 4;
    const float* xp = x + (size_t)k0 * NVOX + v0 + (lane & 7) * 8;
#pragma unroll
    for (int i = 0; i < 4; i++) {
        r.f[2 * i]     = *(const float4*)(xp + (size_t)i * NVOX);
        r.f[2 * i + 1] = *(const float4*)(xp + (size_t)i * NVOX + 4);
    }
}

// buffer: 128 k-rows x 64 vox bf16, 128B rows, 16B-chunk xor (k&7); STS.128 (verified)
__device__ __forceinline__ void sts_tile(uint32_t bufH, int wid, int lane,
                                         const XFrag& r)
{
    const int k0 = wid * 16 + (lane >> 3) * 4;
    const uint32_t voxb = (uint32_t)((lane & 7) * 16);
#pragma unroll
    for (int i = 0; i < 4; i++) {
        const int k = k0 + i;
        float4 fa = r.f[2 * i];
        float4 fb = r.f[2 * i + 1];
        uint32_t h0 = pack_bf16x2(fa.x, fa.y);
        uint32_t h1 = pack_bf16x2(fa.z, fa.w);
        uint32_t h2 = pack_bf16x2(fb.x, fb.y);
        uint32_t h3 = pack_bf16x2(fb.z, fb.w);
        float a0 = __uint_as_float(h0 << 16), a1 = __uint_as_float(h0 & 0xffff0000u);
        float a2 = __uint_as_float(h1 << 16), a3 = __uint_as_float(h1 & 0xffff0000u);
        float a4 = __uint_as_float(h2 << 16), a5 = __uint_as_float(h2 & 0xffff0000u);
        float a6 = __uint_as_float(h3 << 16), a7 = __uint_as_float(h3 & 0xffff0000u);
        uint32_t l0 = pack_bf16x2(fa.x - a0, fa.y - a1);
        uint32_t l1 = pack_bf16x2(fa.z - a2, fa.w - a3);
        uint32_t l2 = pack_bf16x2(fb.x - a4, fb.y - a5);
        uint32_t l3 = pack_bf16x2(fb.z - a6, fb.w - a7);
        uint32_t addr = bufH + (uint32_t)k * 128u
                      + (voxb ^ (uint32_t)((k & 7) << 4));
        sts128(addr,         h0, h1, h2, h3);
        sts128(addr + 16384, l0, l1, l2, l3);
    }
}

__global__ __launch_bounds__(THREADS, 2)
void fused_kernel(const float* __restrict__ x,
                  const float* __restrict__ b,
                  float* __restrict__ out)
{
    extern __shared__ __align__(16) char smem[];
    const uint32_t sbase = smem_u32(smem);
    const int tid  = threadIdx.x;
    const int lane = tid & 31;
    const int wid  = tid >> 5;              // 0..7

    // --- load full W once (64KB) ---
    {
        const float4* Wv = (const float4*)g_Wsw;
        float4* sWv = (float4*)(smem + SM_W);
#pragma unroll
        for (int i = 0; i < 16; i++)
            sWv[tid + THREADS * i] = Wv[tid + THREADS * i];
    }

    const int ocb = (wid & 3) * 32;
    const int vh  = (wid >> 2) * 32;
    const int ocl = ocb + (lane >> 2);

    // A-side ldmatrix ([oc][k] 256B rows, verified)
    const int aRow = ocb + (lane & 15);
    const uint32_t aSw = (uint32_t)((aRow & 7) << 4);
    const uint32_t aK  = (uint32_t)((lane >> 4) * 16);
    const uint32_t aB  = sbase + SM_W + (uint32_t)aRow * 256u;

    // B-side ldmatrix.trans (128B rows, xor (k&7), verified)
    const int bK = lane & 15;
    uint32_t bOff[2];
#pragma unroll
    for (int nbp = 0; nbp < 2; nbp++) {
        uint32_t voxbyte = (uint32_t)(vh * 2 + nbp * 32 + (lane >> 4) * 16);
        bOff[nbp] = (uint32_t)bK * 128u
                  + (voxbyte ^ ((uint32_t)(bK & 7) << 4));
    }

    const float bias0a = __ldg(b + ocl);
    const float bias0b = __ldg(b + ocl + 8);
    const float bias1a = __ldg(b + ocl + 16);
    const float bias1b = __ldg(b + ocl + 24);

    // epilogue chunk identity
    const int myrow = tid >> 4;      // 0..15
    const int mych  = tid & 15;      // 16B chunk (4 vox)
    const unsigned short* attp =
        g_atts2 + (size_t)myrow * NVOX + mych * 4;

    // prologue: tile0 into the single buffer
    int t = blockIdx.x;
    {
        XFrag r0;
        ldg_tile(x, t * TILE_V, wid, lane, r0);
        sts_tile(sbase + SM_XH, wid, lane, r0);
    }
    __syncthreads();

    while (true) {
        const int tn = t + GRID;
        const bool has_next = (tn < NT64);

        // prefetch next x tile into regs
        XFrag rn;
        if (has_next) ldg_tile(x, tn * TILE_V, wid, lane, rn);

        // prefetch epilogue att (coalesced u64 = 4 vox of one oc row)
        unsigned long long av[8];
        {
            const unsigned short* ap = attp + (size_t)t * TILE_V;
#pragma unroll
            for (int it = 0; it < 8; it++)
                av[it] = ldg_u64(ap + (size_t)it * 16 * NVOX);
        }

        // accumulators, init with bias
        float acc[2][4][4];
#pragma unroll
        for (int nb = 0; nb < 4; nb++) {
            acc[0][nb][0] = bias0a; acc[0][nb][1] = bias0a;
            acc[0][nb][2] = bias0b; acc[0][nb][3] = bias0b;
            acc[1][nb][0] = bias1a; acc[1][nb][1] = bias1a;
            acc[1][nb][2] = bias1b; acc[1][nb][3] = bias1b;
        }

        // MMA over 8 k-steps, 3 split terms (verified inner loop)
        const uint32_t bufH = sbase + SM_XH;
        const uint32_t bufL = sbase + SM_XL;
#pragma unroll
        for (int ks = 0; ks < 8; ks++) {
            const uint32_t kbA = ((uint32_t)(ks * 32) + aK) ^ aSw;
            uint32_t a0h[4], a1h[4], a0l[4], a1l[4];
            ldsm_x4(aB + kbA,                a0h);
            ldsm_x4(aB + 4096 + kbA,         a1h);
            ldsm_x4(aB + 32768 + kbA,        a0l);
            ldsm_x4(aB + 32768 + 4096 + kbA, a1l);

            const uint32_t krow = (uint32_t)(ks * 2048);
#pragma unroll
            for (int nbp = 0; nbp < 2; nbp++) {
                uint32_t bh[4], bl[4];
                ldsm_x4_t(bufH + krow + bOff[nbp], bh);
                ldsm_x4_t(bufL + krow + bOff[nbp], bl);
                float* A00 = acc[0][2 * nbp];
                float* A10 = acc[1][2 * nbp];
                float* A01 = acc[0][2 * nbp + 1];
                float* A11 = acc[1][2 * nbp + 1];
                mma16816(A00, a0h, bh[0], bh[1]);
                mma16816(A10, a1h, bh[0], bh[1]);
                mma16816(A01, a0h, bh[2], bh[3]);
                mma16816(A11, a1h, bh[2], bh[3]);
                mma16816(A00, a0h, bl[0], bl[1]);
                mma16816(A10, a1h, bl[0], bl[1]);
                mma16816(A01, a0h, bl[2], bl[3]);
                mma16816(A11, a1h, bl[2], bl[3]);
                mma16816(A00, a0l, bh[0], bh[1]);
                mma16816(A10, a1l, bh[0], bh[1]);
                mma16816(A01, a0l, bh[2], bh[3]);
                mma16816(A11, a1l, bh[2], bh[3]);
            }
        }

        __syncthreads();   // MMA done: x buffer is free

        // stage acc -> smem [oc][vox] fp32, row-XOR swizzle (verified)
#pragma unroll
        for (int tt = 0; tt < 2; tt++) {
            int row0 = ocb + (lane >> 2) + 16 * tt;
            int row1 = row0 + 8;
            uint32_t x0 = (uint32_t)((row0 & 7) << 5);
#pragma unroll
            for (int nb = 0; nb < 4; nb++) {
                uint32_t vb4 = (uint32_t)((vh + 2 * (lane & 3) + 8 * nb) * 4);
                sts64f(sbase + (uint32_t)row0 * 256u + (vb4 ^ x0),
                       acc[tt][nb][0], acc[tt][nb][1]);
                sts64f(sbase + (uint32_t)row1 * 256u + (vb4 ^ x0),
                       acc[tt][nb][2], acc[tt][nb][3]);
            }
        }
        __syncthreads();   // staging visible

        // epilogue: coalesced LDS.128 + att regs + streaming STG.128
        {
            float* ob = out + (size_t)myrow * NVOX + t * TILE_V + mych * 4;
#pragma unroll
            for (int it = 0; it < 8; it++) {
                int row = myrow + it * 16;
                float4 y = lds128f(sbase + (uint32_t)row * 256u
                                   + ((uint32_t)(mych * 16)
                                      ^ (uint32_t)((row & 7) << 5)));
                uint32_t lo = (uint32_t)av[it];
                uint32_t hi = (uint32_t)(av[it] >> 32);
                float4 o;
                o.x = leaky_ep(y.x, bf2f(lo & 0xffffu));
                o.y = leaky_ep(y.y, bf2f(lo >> 16));
                o.z = leaky_ep(y.z, bf2f(hi & 0xffffu));
                o.w = leaky_ep(y.w, bf2f(hi >> 16));
                __stcs((float4*)(ob + (size_t)it * 16 * NVOX), o);
            }
        }
        __syncthreads();   // staging reads done: buffer free for refill

        if (has_next) {
            sts_tile(sbase + SM_XH, wid, lane, rn);
            __syncthreads();   // buffer ready
            t = tn;
        } else {
            break;
        }
    }
}

// ---------------------------------------------------------------------------
extern "C" void kernel_launch(void* const* d_in, const int* in_sizes, int n_in,
                              void* d_out, int out_size)
{
    (void)in_sizes; (void)n_in; (void)out_size;
    const float* x   = (const float*)d_in[0];
    const float* att = (const float*)d_in[1];
    const float* W   = (const float*)d_in[2];
    const float* b   = (const float*)d_in[3];
    float* out = (float*)d_out;

    // 128 oc x 4 id x 9 iwb x 2 halves = 9216 CTAs; first 64 also split W
    prep_kernel<<<9216, 256>>>(att, W);

    cudaFuncSetAttribute(fused_kernel,
                         cudaFuncAttributeMaxDynamicSharedMemorySize,
                         SMEM_TOTAL);
    fused_kernel<<<GRID, THREADS, SMEM_TOTAL>>>(x, b, out);
}

// round 15
// speedup vs baseline: 1.0557x; 1.0557x over previous
#include <cuda_runtime.h>
#include <cuda_bf16.h>
#include <cstdint>

// ---------------------------------------------------------------------------
//   y   = W @ x + b   (oc=128, cin=128, vox=186624)
//   out = leaky_0.2( y * (y + att[c,l,pp]/nz[c,l] + 1) )
// GEMM on mma.sync m16n8k16 (bf16) via 3-way split: Wh*xh + Wh*xl + Wl*xh
// R15: prep = R13 shape (4608 CTAs, warp owns 2x4-row groups) with BOTH
//      groups' loads hoisted (6 LDG.128 in flight). Fused = R14 verbatim.
// ---------------------------------------------------------------------------

#define CIN    128
#define COUT   128
#define HWDIM  5184
#define NVOX   186624
#define PATCH  9
#define PPSQ   81
#define NW     576
#define LPATCH 2304

#define TILE_V  64
#define NT64    2916          // NVOX / 64
#define GRID    296           // 2 CTAs per SM
#define THREADS 256

// per-CTA dynamic smem (bytes):
//   x stage: xh 16KB @0, xl 16KB @16384 (reused as 32KB fp32 out-stage)
//   W: Wh 32KB @32768, Wl 32KB @65536
#define SM_XH 0
#define SM_XL 16384
#define SM_W  32768
#define SMEM_TOTAL 98304      // 96KB -> 2 CTAs/SM

__device__ __align__(16) unsigned short g_Wsw[32768];        // [Wh][Wl], swizzled
__device__ __align__(16) unsigned short g_atts2[COUT * NVOX]; // bf16 att/nz, voxel-major

// ---------------------------------------------------------------------------
// helpers
// ---------------------------------------------------------------------------
__device__ __forceinline__ uint32_t smem_u32(const void* p) {
    uint32_t a;
    asm("{ .reg .u64 t; cvta.to.shared.u64 t, %1; cvt.u32.u64 %0, t; }"
        : "=r"(a) : "l"(p));
    return a;
}
__device__ __forceinline__ uint32_t pack_bf16x2(float lo, float hi) {
    uint32_t r;
    asm("cvt.rn.bf16x2.f32 %0, %1, %2;" : "=r"(r) : "f"(hi), "f"(lo));
    return r;
}
__device__ __forceinline__ int redux_add(int v) {
    int r;
    asm("redux.sync.add.s32 %0, %1, 0xffffffff;" : "=r"(r) : "r"(v));
    return r;
}
__device__ __forceinline__ void sts128(uint32_t addr, uint32_t a, uint32_t b,
                                       uint32_t c, uint32_t d) {
    asm volatile("st.shared.v4.u32 [%0], {%1, %2, %3, %4};"
                 :: "r"(addr), "r"(a), "r"(b), "r"(c), "r"(d) : "memory");
}
__device__ __forceinline__ void sts64f(uint32_t addr, float a, float b) {
    asm volatile("st.shared.v2.f32 [%0], {%1, %2};"
                 :: "r"(addr), "f"(a), "f"(b) : "memory");
}
__device__ __forceinline__ float4 lds128f(uint32_t addr) {
    float4 v;
    asm volatile("ld.shared.v4.f32 {%0,%1,%2,%3}, [%4];"
                 : "=f"(v.x), "=f"(v.y), "=f"(v.z), "=f"(v.w) : "r"(addr));
    return v;
}
__device__ __forceinline__ void ldsm_x4(uint32_t addr, uint32_t* r) {
    asm volatile("ldmatrix.sync.aligned.m8n8.x4.shared.b16 {%0,%1,%2,%3}, [%4];"
                 : "=r"(r[0]), "=r"(r[1]), "=r"(r[2]), "=r"(r[3]) : "r"(addr));
}
__device__ __forceinline__ void ldsm_x4_t(uint32_t addr, uint32_t* r) {
    asm volatile("ldmatrix.sync.aligned.m8n8.x4.trans.shared.b16 {%0,%1,%2,%3}, [%4];"
                 : "=r"(r[0]), "=r"(r[1]), "=r"(r[2]), "=r"(r[3]) : "r"(addr));
}
__device__ __forceinline__ void mma16816(float* d, const uint32_t* a,
                                         uint32_t b0, uint32_t b1) {
    asm volatile(
        "mma.sync.aligned.m16n8k16.row.col.f32.bf16.bf16.f32 "
        "{%0,%1,%2,%3}, {%4,%5,%6,%7}, {%8,%9}, {%0,%1,%2,%3};"
        : "+f"(d[0]), "+f"(d[1]), "+f"(d[2]), "+f"(d[3])
        : "r"(a[0]), "r"(a[1]), "r"(a[2]), "r"(a[3]), "r"(b0), "r"(b1));
}
__device__ __forceinline__ unsigned long long ldg_u64(const void* p) {
    unsigned long long v;
    asm volatile("ld.global.nc.u64 %0, [%1];" : "=l"(v) : "l"(p));
    return v;
}
__device__ __forceinline__ float bf2f(uint32_t v16) {
    return __uint_as_float(v16 << 16);
}
__device__ __forceinline__ float sel4(int r, float a, float b, float c, float d) {
    float v = a;
    v = (r == 1) ? b : v;
    v = (r == 2) ? c : v;
    v = (r == 3) ? d : v;
    return v;
}
__device__ __forceinline__ float leaky_ep(float y, float a) {
    float o = y * (y + a + 1.0f);
    return (o >= 0.0f) ? o : 0.2f * o;
}
// W-tile swizzle (256B rows, verified)
__device__ __forceinline__ uint32_t swz(int row, uint32_t colbyte) {
    return (uint32_t)row * 256u + (colbyte ^ (uint32_t)((row & 7) << 4));
}

// ---------------------------------------------------------------------------
// Prep v6: W split (verified) + att -> voxel-major bf16(att/nz).
// 4608 CTAs; warp owns 2 groups of 4 rows; BOTH groups' loads hoisted first
// (6 independent LDG.128/thread), then redux counts + scatter from registers,
// then coalesced uint4 copy-out (R13-verified mapping).
// ---------------------------------------------------------------------------
__device__ __forceinline__ void prep_process(const float4* f, int g, int lane,
                                             unsigned short* obuf)
{
    // counts per row (verified logic)
    int c0 = 0, c1 = 0, c2 = 0, c3 = 0;
#pragma unroll
    for (int p = 0; p < 3; p++) {
        int idx = p * 32 + lane;
        if (idx < 81) {
            float4 q = f[p];
            int e = idx * 4;
            int r0 = (e >= 81) + (e >= 162) + (e >= 243);
            int r3 = (e + 3 >= 81) + (e + 3 >= 162) + (e + 3 >= 243);
            if (r0 == r3) {
                int cnt = (q.x != 0.f) + (q.y != 0.f) + (q.z != 0.f) + (q.w != 0.f);
                c0 += (r0 == 0) ? cnt : 0;
                c1 += (r0 == 1) ? cnt : 0;
                c2 += (r0 == 2) ? cnt : 0;
                c3 += (r0 == 3) ? cnt : 0;
            } else {
                float vv[4] = { q.x, q.y, q.z, q.w };
#pragma unroll
                for (int j = 0; j < 4; j++) {
                    int ej = e + j;
                    int rj = (ej >= 81) + (ej >= 162) + (ej >= 243);
                    int nz = (vv[j] != 0.f);
                    c0 += (rj == 0) ? nz : 0;
                    c1 += (rj == 1) ? nz : 0;
                    c2 += (rj == 2) ? nz : 0;
                    c3 += (rj == 3) ? nz : 0;
                }
            }
        }
    }
    c0 = redux_add(c0); c1 = redux_add(c1);
    c2 = redux_add(c2); c3 = redux_add(c3);
    float i0 = 1.0f / ((float)c0 + 1e-5f);
    float i1 = 1.0f / ((float)c1 + 1e-5f);
    float i2 = 1.0f / ((float)c2 + 1e-5f);
    float i3 = 1.0f / ((float)c3 + 1e-5f);

    // scale + scatter into voxel-major staging (R13-verified mapping)
#pragma unroll
    for (int p = 0; p < 3; p++) {
        int idx = p * 32 + lane;
        if (idx < 81) {
            float4 q = f[p];
            float vv[4] = { q.x, q.y, q.z, q.w };
            int e = idx * 4;
#pragma unroll
            for (int j = 0; j < 4; j++) {
                int ej = e + j;
                int rj = (ej >= 81) + (ej >= 162) + (ej >= 243);
                int ppj = ej - rj * 81;
                int pd = ppj / 9;
                int pw = ppj - pd * 9;
                int row = g * 4 + rj;
                float s = sel4(rj, i0, i1, i2, i3);
                __nv_bfloat16 u = __float2bfloat16(vv[j] * s);
                obuf[pd * 576 + row * 9 + pw] = *(unsigned short*)&u;
            }
        }
    }
}

__global__ __launch_bounds__(256) void prep_kernel(const float* __restrict__ att,
                                                   const float* __restrict__ W)
{
    __shared__ unsigned short obuf[9 * 576];   // 10368 B staging

    const int tid = threadIdx.x;
    const int blk = blockIdx.x;

    if (blk < 64) {   // W split (verified)
        int idx = blk * 256 + tid;
        int oc = idx >> 7, k = idx & 127;
        float w = W[idx];
        __nv_bfloat16 h = __float2bfloat16(w);
        float hf = __bfloat162float(h);
        __nv_bfloat16 l = __float2bfloat16(w - hf);
        uint32_t off = swz(oc, (uint32_t)(k * 2)) >> 1;
        g_Wsw[off]         = *(unsigned short*)&h;
        g_Wsw[off + 16384] = *(unsigned short*)&l;
    }

    const int oc  = blk / 36;
    const int rem = blk - oc * 36;
    const int id  = rem / 9;
    const int iwb = rem - id * 9;
    const int wid = tid >> 5;
    const int lane = tid & 31;

    // slab base (64 rows x 81 floats = 1296 float4)
    const float4* slab = (const float4*)(att
        + (size_t)(oc * LPATCH + id * 576 + iwb * 64) * PPSQ);
    const float4* a0 = slab + (size_t)(2 * wid) * 81;
    const float4* a1 = a0 + 81;

    // hoisted loads: both groups, 6 independent LDG.128 in flight
    float4 f0[3], f1[3];
#pragma unroll
    for (int p = 0; p < 3; p++) {
        int idx = p * 32 + lane;
        if (idx < 81) {
            f0[p] = __ldg(a0 + idx);
            f1[p] = __ldg(a1 + idx);
        }
    }

    prep_process(f0, 2 * wid,     lane, obuf);
    prep_process(f1, 2 * wid + 1, lane, obuf);
    __syncthreads();

    // coalesced copy-out (648 uint4) — verified R13 mapping
    {
        const uint4* src = (const uint4*)obuf;
        unsigned short* dstbase = g_atts2
            + (size_t)oc * NVOX + (size_t)(id * 9) * HWDIM + iwb * 576;
        for (int q = tid; q < 648; q += 256) {
            int pd = q / 72;
            int w  = q - pd * 72;
            *(uint4*)(dstbase + (size_t)pd * HWDIM + w * 8) = src[q];
        }
    }
}

// ---------------------------------------------------------------------------
// Fused persistent kernel: CTA = 128 oc x 64 vox, 8 warps (4 oc x 2 vox),
// warp tile 32 oc x 32 vox, single-buffered x, 2 CTAs/SM, smem out-restage.
// (R14 verbatim — verified 64.8us)
// ---------------------------------------------------------------------------
struct XFrag { float4 f[8]; };

__device__ __forceinline__ void ldg_tile(const float* __restrict__ x,
                                         int v0, int wid, int lane, XFrag& r)
{
    const int k0 = wid * 16 + (lane >> 3) * 4;
    const float* xp = x + (size_t)k0 * NVOX + v0 + (lane & 7) * 8;
#pragma unroll
    for (int i = 0; i < 4; i++) {
        r.f[2 * i]     = *(const float4*)(xp + (size_t)i * NVOX);
        r.f[2 * i + 1] = *(const float4*)(xp + (size_t)i * NVOX + 4);
    }
}

__device__ __forceinline__ void sts_tile(uint32_t bufH, int wid, int lane,
                                         const XFrag& r)
{
    const int k0 = wid * 16 + (lane >> 3) * 4;
    const uint32_t voxb = (uint32_t)((lane & 7) * 16);
#pragma unroll
    for (int i = 0; i < 4; i++) {
        const int k = k0 + i;
        float4 fa = r.f[2 * i];
        float4 fb = r.f[2 * i + 1];
        uint32_t h0 = pack_bf16x2(fa.x, fa.y);
        uint32_t h1 = pack_bf16x2(fa.z, fa.w);
        uint32_t h2 = pack_bf16x2(fb.x, fb.y);
        uint32_t h3 = pack_bf16x2(fb.z, fb.w);
        float a0 = __uint_as_float(h0 << 16), a1 = __uint_as_float(h0 & 0xffff0000u);
        float a2 = __uint_as_float(h1 << 16), a3 = __uint_as_float(h1 & 0xffff0000u);
        float a4 = __uint_as_float(h2 << 16), a5 = __uint_as_float(h2 & 0xffff0000u);
        float a6 = __uint_as_float(h3 << 16), a7 = __uint_as_float(h3 & 0xffff0000u);
        uint32_t l0 = pack_bf16x2(fa.x - a0, fa.y - a1);
        uint32_t l1 = pack_bf16x2(fa.z - a2, fa.w - a3);
        uint32_t l2 = pack_bf16x2(fb.x - a4, fb.y - a5);
        uint32_t l3 = pack_bf16x2(fb.z - a6, fb.w - a7);
        uint32_t addr = bufH + (uint32_t)k * 128u
                      + (voxb ^ (uint32_t)((k & 7) << 4));
        sts128(addr,         h0, h1, h2, h3);
        sts128(addr + 16384, l0, l1, l2, l3);
    }
}

__global__ __launch_bounds__(THREADS, 2)
void fused_kernel(const float* __restrict__ x,
                  const float* __restrict__ b,
                  float* __restrict__ out)
{
    extern __shared__ __align__(16) char smem[];
    const uint32_t sbase = smem_u32(smem);
    const int tid  = threadIdx.x;
    const int lane = tid & 31;
    const int wid  = tid >> 5;              // 0..7

    // --- load full W once (64KB) ---
    {
        const float4* Wv = (const float4*)g_Wsw;
        float4* sWv = (float4*)(smem + SM_W);
#pragma unroll
        for (int i = 0; i < 16; i++)
            sWv[tid + THREADS * i] = Wv[tid + THREADS * i];
    }

    const int ocb = (wid & 3) * 32;
    const int vh  = (wid >> 2) * 32;
    const int ocl = ocb + (lane >> 2);

    // A-side ldmatrix ([oc][k] 256B rows, verified)
    const int aRow = ocb + (lane & 15);
    const uint32_t aSw = (uint32_t)((aRow & 7) << 4);
    const uint32_t aK  = (uint32_t)((lane >> 4) * 16);
    const uint32_t aB  = sbase + SM_W + (uint32_t)aRow * 256u;

    // B-side ldmatrix.trans (128B rows, xor (k&7), verified)
    const int bK = lane & 15;
    uint32_t bOff[2];
#pragma unroll
    for (int nbp = 0; nbp < 2; nbp++) {
        uint32_t voxbyte = (uint32_t)(vh * 2 + nbp * 32 + (lane >> 4) * 16);
        bOff[nbp] = (uint32_t)bK * 128u
                  + (voxbyte ^ ((uint32_t)(bK & 7) << 4));
    }

    const float bias0a = __ldg(b + ocl);
    const float bias0b = __ldg(b + ocl + 8);
    const float bias1a = __ldg(b + ocl + 16);
    const float bias1b = __ldg(b + ocl + 24);

    // epilogue chunk identity
    const int myrow = tid >> 4;      // 0..15
    const int mych  = tid & 15;      // 16B chunk (4 vox)
    const unsigned short* attp =
        g_atts2 + (size_t)myrow * NVOX + mych * 4;

    // prologue: tile0 into the single buffer
    int t = blockIdx.x;
    {
        XFrag r0;
        ldg_tile(x, t * TILE_V, wid, lane, r0);
        sts_tile(sbase + SM_XH, wid, lane, r0);
    }
    __syncthreads();

    while (true) {
        const int tn = t + GRID;
        const bool has_next = (tn < NT64);

        // prefetch next x tile into regs
        XFrag rn;
        if (has_next) ldg_tile(x, tn * TILE_V, wid, lane, rn);

        // prefetch epilogue att (coalesced u64 = 4 vox of one oc row)
        unsigned long long av[8];
        {
            const unsigned short* ap = attp + (size_t)t * TILE_V;
#pragma unroll
            for (int it = 0; it < 8; it++)
                av[it] = ldg_u64(ap + (size_t)it * 16 * NVOX);
        }

        // accumulators, init with bias
        float acc[2][4][4];
#pragma unroll
        for (int nb = 0; nb < 4; nb++) {
            acc[0][nb][0] = bias0a; acc[0][nb][1] = bias0a;
            acc[0][nb][2] = bias0b; acc[0][nb][3] = bias0b;
            acc[1][nb][0] = bias1a; acc[1][nb][1] = bias1a;
            acc[1][nb][2] = bias1b; acc[1][nb][3] = bias1b;
        }

        // MMA over 8 k-steps, 3 split terms (verified inner loop)
        const uint32_t bufH = sbase + SM_XH;
        const uint32_t bufL = sbase + SM_XL;
#pragma unroll
        for (int ks = 0; ks < 8; ks++) {
            const uint32_t kbA = ((uint32_t)(ks * 32) + aK) ^ aSw;
            uint32_t a0h[4], a1h[4], a0l[4], a1l[4];
            ldsm_x4(aB + kbA,                a0h);
            ldsm_x4(aB + 4096 + kbA,         a1h);
            ldsm_x4(aB + 32768 + kbA,        a0l);
            ldsm_x4(aB + 32768 + 4096 + kbA, a1l);

            const uint32_t krow = (uint32_t)(ks * 2048);
#pragma unroll
            for (int nbp = 0; nbp < 2; nbp++) {
                uint32_t bh[4], bl[4];
                ldsm_x4_t(bufH + krow + bOff[nbp], bh);
                ldsm_x4_t(bufL + krow + bOff[nbp], bl);
                float* A00 = acc[0][2 * nbp];
                float* A10 = acc[1][2 * nbp];
                float* A01 = acc[0][2 * nbp + 1];
                float* A11 = acc[1][2 * nbp + 1];
                mma16816(A00, a0h, bh[0], bh[1]);
                mma16816(A10, a1h, bh[0], bh[1]);
                mma16816(A01, a0h, bh[2], bh[3]);
                mma16816(A11, a1h, bh[2], bh[3]);
                mma16816(A00, a0h, bl[0], bl[1]);
                mma16816(A10, a1h, bl[0], bl[1]);
                mma16816(A01, a0h, bl[2], bl[3]);
                mma16816(A11, a1h, bl[2], bl[3]);
                mma16816(A00, a0l, bh[0], bh[1]);
                mma16816(A10, a1l, bh[0], bh[1]);
                mma16816(A01, a0l, bh[2], bh[3]);
                mma16816(A11, a1l, bh[2], bh[3]);
            }
        }

        __syncthreads();   // MMA done: x buffer is free

        // stage acc -> smem [oc][vox] fp32, row-XOR swizzle (verified)
#pragma unroll
        for (int tt = 0; tt < 2; tt++) {
            int row0 = ocb + (lane >> 2) + 16 * tt;
            int row1 = row0 + 8;
            uint32_t x0 = (uint32_t)((row0 & 7) << 5);
#pragma unroll
            for (int nb = 0; nb < 4; nb++) {
                uint32_t vb4 = (uint32_t)((vh + 2 * (lane & 3) + 8 * nb) * 4);
                sts64f(sbase + (uint32_t)row0 * 256u + (vb4 ^ x0),
                       acc[tt][nb][0], acc[tt][nb][1]);
                sts64f(sbase + (uint32_t)row1 * 256u + (vb4 ^ x0),
                       acc[tt][nb][2], acc[tt][nb][3]);
            }
        }
        __syncthreads();   // staging visible

        // epilogue: coalesced LDS.128 + att regs + streaming STG.128
        {
            float* ob = out + (size_t)myrow * NVOX + t * TILE_V + mych * 4;
#pragma unroll
            for (int it = 0; it < 8; it++) {
                int row = myrow + it * 16;
                float4 y = lds128f(sbase + (uint32_t)row * 256u
                                   + ((uint32_t)(mych * 16)
                                      ^ (uint32_t)((row & 7) << 5)));
                uint32_t lo = (uint32_t)av[it];
                uint32_t hi = (uint32_t)(av[it] >> 32);
                float4 o;
                o.x = leaky_ep(y.x, bf2f(lo & 0xffffu));
                o.y = leaky_ep(y.y, bf2f(lo >> 16));
                o.z = leaky_ep(y.z, bf2f(hi & 0xffffu));
                o.w = leaky_ep(y.w, bf2f(hi >> 16));
                __stcs((float4*)(ob + (size_t)it * 16 * NVOX), o);
            }
        }
        __syncthreads();   // staging reads done: buffer free for refill

        if (has_next) {
            sts_tile(sbase + SM_XH, wid, lane, rn);
            __syncthreads();   // buffer ready
            t = tn;
        } else {
            break;
        }
    }
}

// ---------------------------------------------------------------------------
extern "C" void kernel_launch(void* const* d_in, const int* in_sizes, int n_in,
                              void* d_out, int out_size)
{
    (void)in_sizes; (void)n_in; (void)out_size;
    const float* x   = (const float*)d_in[0];
    const float* att = (const float*)d_in[1];
    const float* W   = (const float*)d_in[2];
    const float* b   = (const float*)d_in[3];
    float* out = (float*)d_out;

    // 128 oc x 4 id x 9 iw-blocks = 4608 CTAs; first 64 also split W
    prep_kernel<<<4608, 256>>>(att, W);

    cudaFuncSetAttribute(fused_kernel,
                         cudaFuncAttributeMaxDynamicSharedMemorySize,
                         SMEM_TOTAL);
    fused_kernel<<<GRID, THREADS, SMEM_TOTAL>>>(x, b, out);
}